// round 15
// baseline (speedup 1.0000x reference)
#include <cuda_runtime.h>
#include <cstdint>

// Problem constants
#define TV      16384   // T * V
#define CTX     16      // T
#define VOCABSZ 1024    // V
#define NB      256     // batch
#define KSLOT   16      // 4096 / 256 staging slots per thread
#define NCTA    444     // 148 SMs x 3 CTAs: exactly one resident wave

// out[b, j] = relu( bias[j] + sum_t W[j, x[b,t] + t*V] )
//
// Fused-compaction, single-wave kernel. Only ~3620 of 16384 columns of W
// are ever indexed; each CTA builds the sorted unique column list U and
// per-batch rank map in smem ONCE (~2.8us), then streams a CONTIGUOUS
// range of ~37 rows (~160us of work) gathering only those columns with
// sorted __ldcg loads + a register prefetch pipeline. grid=444 (= 148x3)
// makes every CTA resident for the whole kernel, so prep overhead is 1.8%
// (vs 8% at grid 2048 in R14) and there is no wave-quantization tail.

__global__ __launch_bounds__(256, 3)
void lr_wave_kernel(const int*   __restrict__ x,
                    const float* __restrict__ W,
                    const float* __restrict__ bias,
                    float*       __restrict__ out)
{
    __shared__ uint32_t bm[512];      // 16384-bit column bitmap   (2 KB)
    __shared__ int      base_s[512];  // exclusive popcount prefix (2 KB)
    __shared__ int      s_U[TV / 4];  // unique sorted columns     (16 KB)
    __shared__ float    s_g[TV / 4];  // staged gathered values    (16 KB)
    __shared__ int      s_nu;

    const int tid = threadIdx.x;      // = batch index b
    const int bid = blockIdx.x;

    // Contiguous row range: 16384 = 444*36 + 400 -> bid<400 owns 37 rows.
    const int start  = 36 * bid + ((bid < 400) ? bid : 400);
    const int n_rows = 36 + (bid < 400 ? 1 : 0);

    // ---------- prep (once per CTA, amortized over ~160us) ----------
    bm[tid] = 0; bm[tid + 256] = 0;
    __syncthreads();

    // This thread's 16 columns (x is int32 on device; JAX downcasts int64).
    int cols[CTX];
    {
        const int4* xb = (const int4*)(x + tid * CTX);
        #pragma unroll
        for (int q = 0; q < CTX / 4; q++) {
            int4 v = xb[q];
            cols[q * 4 + 0] = v.x + (q * 4 + 0) * VOCABSZ;
            cols[q * 4 + 1] = v.y + (q * 4 + 1) * VOCABSZ;
            cols[q * 4 + 2] = v.z + (q * 4 + 2) * VOCABSZ;
            cols[q * 4 + 3] = v.w + (q * 4 + 3) * VOCABSZ;
        }
    }
    #pragma unroll
    for (int t = 0; t < CTX; t++)
        atomicOr(&bm[cols[t] >> 5], 1u << (cols[t] & 31));
    __syncthreads();

    // Warp 0: serial-per-lane + warp scan over 512 word popcounts.
    if (tid < 32) {
        int loc[16], tot = 0;
        #pragma unroll
        for (int k = 0; k < 16; k++) {
            loc[k] = tot;
            tot += __popc(bm[tid * 16 + k]);
        }
        int v = tot;
        #pragma unroll
        for (int off = 1; off < 32; off <<= 1) {
            int n = __shfl_up_sync(0xffffffffu, v, off);
            if (tid >= off) v += n;
        }
        int ebase = v - tot;
        #pragma unroll
        for (int k = 0; k < 16; k++)
            base_s[tid * 16 + k] = ebase + loc[k];
        if (tid == 31) s_nu = v;
    }
    __syncthreads();

    // Emit unique sorted column list into smem.
    for (int w = tid; w < 512; w += 256) {
        uint32_t bits = bm[w];
        int idx = base_s[w];
        while (bits) {
            int b = __ffs(bits) - 1;
            s_U[idx++] = w * 32 + b;
            bits &= bits - 1;
        }
    }
    // Pad tail so slot loads are unconditional (dups of col 0: cache hit).
    for (int i = s_nu + tid; i < TV / 4; i += 256)
        s_U[i] = 0;

    // Rank of each of this thread's columns.
    int m[CTX];
    #pragma unroll
    for (int t = 0; t < CTX; t++) {
        int w = cols[t] >> 5;
        m[t] = base_s[w] + __popc(bm[w] & ((1u << (cols[t] & 31)) - 1u));
    }
    __syncthreads();

    // Staging slots owned by this thread (same columns every row).
    int u_idx[KSLOT];
    #pragma unroll
    for (int k = 0; k < KSLOT; k++)
        u_idx[k] = s_U[tid + 256 * k];

    // ---------- row pipeline (R13 structure, variable-length range) ------
    // Prefetch first row's gathers (sorted cols -> ~5 lines/warp; L2-only).
    float pf[KSLOT];
    {
        const float* rowp = W + (size_t)start * TV;
        #pragma unroll
        for (int k = 0; k < KSLOT; k++)
            pf[k] = __ldcg(rowp + u_idx[k]);
    }

    float acc[8];

    #pragma unroll 1
    for (int q = 0; q < n_rows; q++) {
        // Publish prefetched row.
        #pragma unroll
        for (int k = 0; k < KSLOT; k++)
            s_g[tid + 256 * k] = pf[k];
        __syncthreads();

        // Issue next row's gathers; latency overlaps the smem accumulate.
        if (q + 1 < n_rows) {
            const float* rowp = W + (size_t)(start + q + 1) * TV;
            #pragma unroll
            for (int k = 0; k < KSLOT; k++)
                pf[k] = __ldcg(rowp + u_idx[k]);
        }

        // Accumulate this thread's 16 picks.
        float s = 0.f;
        #pragma unroll
        for (int t = 0; t < CTX; t++)
            s += s_g[m[t]];
        acc[q & 7] = s;

        __syncthreads();   // all reads done before s_g is overwritten

        // Flush an 8-row (or remainder) block: per-thread consecutive
        // floats at out[b*TV + jblk ..], overlapped with in-flight loads.
        if ((q & 7) == 7 || q == n_rows - 1) {
            const int jblk = start + (q & ~7);
            const int kcnt = (q & 7) + 1;
            float* op = out + (size_t)tid * TV + jblk;
            #pragma unroll
            for (int kk = 0; kk < 8; kk++)
                if (kk < kcnt)
                    op[kk] = fmaxf(acc[kk] + __ldg(bias + jblk + kk), 0.f);
        }
    }
}

extern "C" void kernel_launch(void* const* d_in, const int* in_sizes, int n_in,
                              void* d_out, int out_size)
{
    // Identify inputs by element count:
    //   x: 256*16 = 4096 (int32), W: 16384*16384 (f32), b: 16384 (f32)
    const int*   x    = nullptr;
    const float* W    = nullptr;
    const float* bias = nullptr;
    for (int i = 0; i < n_in; i++) {
        if (in_sizes[i] == NB * CTX)          x    = (const int*)d_in[i];
        else if (in_sizes[i] == TV)           bias = (const float*)d_in[i];
        else                                  W    = (const float*)d_in[i];
    }
    float* out = (float*)d_out;

    lr_wave_kernel<<<NCTA, 256>>>(x, W, bias, out);   // 444 CTAs, one wave
}